// round 16
// baseline (speedup 1.0000x reference)
#include <cuda_runtime.h>
#include <cuda_fp16.h>
#include <cstdint>

#define B_ 2
#define S_ 2048
#define D_ 1024
#define H_ 16
#define DH_ 64
#define NG_ 204
#define SCALE_ 0.125f

// ---------------- scratch (static device globals; no allocations) ----------------
__device__ __half g_Qh[B_ * H_ * S_ * DH_];   // [bh][s][d], pre-scaled by SCALE_
__device__ __half g_Ql[B_ * H_ * S_ * DH_];
__device__ __half g_K [B_ * H_ * S_ * DH_];
__device__ __half g_V [B_ * H_ * S_ * DH_];
__device__ __half g_Kg[B_ * H_ * 256 * DH_];
__device__ __half g_Vg[B_ * H_ * 256 * DH_];
__device__ __half g_Xh[B_ * S_ * D_];
__device__ __half g_Xl[B_ * S_ * D_];         // lo used only by K projection
__device__ __half g_Fh[B_ * S_ * D_];         // fused (gate output), single fp16
__device__ __half g_Wt[4 * D_ * D_];          // W^T [z][n][k] single fp16
__device__ __half g_Wktl[D_ * D_];            // Wk^T lo
__device__ __half g_Wgt[128 * 64];            // Wg^T
__device__ __half g_cath[(size_t)B_ * H_ * S_ * 128];  // [row][local 64 | global 64]
__device__ float  g_knorm[B_ * H_ * S_];

// ================= mma.sync helpers =================
__device__ __forceinline__ void mma_f16(float* c, const uint32_t* a, const uint32_t* b) {
    asm volatile(
        "mma.sync.aligned.m16n8k16.row.col.f32.f16.f16.f32 "
        "{%0,%1,%2,%3}, {%4,%5,%6,%7}, {%8,%9}, {%0,%1,%2,%3};"
        : "+f"(c[0]), "+f"(c[1]), "+f"(c[2]), "+f"(c[3])
        : "r"(a[0]), "r"(a[1]), "r"(a[2]), "r"(a[3]), "r"(b[0]), "r"(b[1]));
}
__device__ __forceinline__ void ldsm4(uint32_t* r, uint32_t addr) {
    asm volatile("ldmatrix.sync.aligned.m8n8.x4.shared.b16 {%0,%1,%2,%3}, [%4];"
                 : "=r"(r[0]), "=r"(r[1]), "=r"(r[2]), "=r"(r[3]) : "r"(addr));
}
__device__ __forceinline__ void ldsm4t(uint32_t* r, uint32_t addr) {
    asm volatile("ldmatrix.sync.aligned.m8n8.x4.trans.shared.b16 {%0,%1,%2,%3}, [%4];"
                 : "=r"(r[0]), "=r"(r[1]), "=r"(r[2]), "=r"(r[3]) : "r"(addr));
}
__device__ __forceinline__ void cp16(uint32_t dst, const void* src) {
    asm volatile("cp.async.cg.shared.global [%0], [%1], 16;" :: "r"(dst), "l"(src));
}
__device__ __forceinline__ void cp_commit() { asm volatile("cp.async.commit_group;"); }
__device__ __forceinline__ void cp_wait0()  { asm volatile("cp.async.wait_group 0;"); }

__device__ __forceinline__ void split2h(float x0, float x1, uint32_t& hi, uint32_t& lo) {
    __half h0 = __float2half(x0);
    __half h1 = __float2half(x1);
    float r0 = x0 - __half2float(h0);
    float r1 = x1 - __half2float(h1);
    __half2 Hh = __halves2half2(h0, h1);
    __half2 Ll = __halves2half2(__float2half(r0), __float2half(r1));
    hi = *reinterpret_cast<uint32_t*>(&Hh);
    lo = *reinterpret_cast<uint32_t*>(&Ll);
}
__device__ __forceinline__ uint32_t pack2h(float x0, float x1) {
    __half2 h = __halves2half2(__float2half(x0), __float2half(x1));
    return *reinterpret_cast<uint32_t*>(&h);
}

// ================= pre-conversion kernels =================
__global__ void conv_x(const float* __restrict__ x) {
    int idx = blockIdx.x * 256 + threadIdx.x;
    float4 v = *(const float4*)(x + (size_t)idx * 4);
    uint32_t h0, l0, h1, l1;
    split2h(v.x, v.y, h0, l0);
    split2h(v.z, v.w, h1, l1);
    *(uint2*)(g_Xh + (size_t)idx * 4) = make_uint2(h0, h1);
    *(uint2*)(g_Xl + (size_t)idx * 4) = make_uint2(l0, l1);
}

__global__ void conv_wt(const float* __restrict__ W0, const float* __restrict__ W1,
                        const float* __restrict__ W2, const float* __restrict__ W3) {
    __shared__ float t[32][33];
    const int z = blockIdx.z;
    const float* W = (z == 0) ? W0 : (z == 1) ? W1 : (z == 2) ? W2 : W3;
    const int n0 = blockIdx.x * 32, k0 = blockIdx.y * 32;
    const int tx = threadIdx.x, ty = threadIdx.y;
#pragma unroll
    for (int i = 0; i < 4; i++)
        t[ty + i * 8][tx] = W[(size_t)(k0 + ty + i * 8) * D_ + n0 + tx];
    __syncthreads();
    size_t ob = (size_t)z * D_ * D_;
#pragma unroll
    for (int i = 0; i < 4; i++) {
        float v = t[tx][ty + i * 8];
        __half h = __float2half(v);
        size_t o = (size_t)(n0 + ty + i * 8) * D_ + k0 + tx;
        g_Wt[ob + o] = h;
        if (z == 1) g_Wktl[o] = __float2half(v - __half2float(h));
    }
}

__global__ void conv_wg(const float* __restrict__ Wg) {
    int t = blockIdx.x * 256 + threadIdx.x;
    int k = t >> 6, n = t & 63;
    g_Wgt[n * 128 + k] = __float2half(Wg[t]);
}

// ================= fused Q+V projection (shared A staging, 1-term each) =================
#define QVR 144
#define QV_A 0
#define QV_BQ 18432
#define QV_BV 27648
#define QV_STG 36864
#define QV_SMEM 73728
#define CSP 66

__global__ void __launch_bounds__(256, 2)
gemm_qv() {
    extern __shared__ char smc[];
    const uint32_t smb = (uint32_t)__cvta_generic_to_shared(smc);
    float* Cs = (float*)smc;

    const int tid = threadIdx.x;
    const int wid = tid >> 5;
    const int lane = tid & 31;
    const int n0 = blockIdx.x * 64;
    const int m0 = blockIdx.y * 128;

    const int warp_m0 = (wid & 3) * 32;
    const int warp_n0 = (wid >> 2) * 32;

    auto stage = [&](int ch) {
        uint32_t sb = smb + (uint32_t)(ch & 1) * QV_STG;
        const int K0 = ch * 64;
#pragma unroll
        for (int i = 0; i < 4; i++) {    // A: 1024 cp16
            int e = tid + i * 256;
            int r = e >> 3, c = e & 7;
            cp16(sb + QV_A + r * QVR + c * 16,
                 g_Xh + (size_t)(m0 + r) * D_ + K0 + c * 8);
        }
#pragma unroll
        for (int i = 0; i < 4; i++) {    // Bq + Bv: 1024 cp16
            int e = tid + i * 256;
            int sel = e >> 9, n = (e >> 3) & 63, c = e & 7;
            const __half* src = g_Wt + (size_t)(sel ? 2 : 0) * D_ * D_ +
                                (size_t)(n0 + n) * D_ + K0 + c * 8;
            cp16(sb + (sel ? QV_BV : QV_BQ) + n * QVR + c * 16, src);
        }
        cp_commit();
    };

    float accq[2][4][4] = {};
    float accv[2][4][4] = {};

    const int lrm = lane & 7;
    const int lmat = lane >> 3;
    const int a_row = lrm + (lmat & 1) * 8;
    const int a_koff = (lmat >> 1) * 16;
    const int b_row = lrm + (lmat >> 1) * 8;
    const int b_koff = (lmat & 1) * 16;

    stage(0);
    for (int ch = 0; ch < 16; ch++) {
        cp_wait0();
        __syncthreads();
        if (ch + 1 < 16) stage(ch + 1);
        const uint32_t sb = smb + (uint32_t)(ch & 1) * QV_STG;

#pragma unroll
        for (int ks = 0; ks < 4; ks++) {
            uint32_t ah[2][4], b[2][4];
#pragma unroll
            for (int mt = 0; mt < 2; mt++)
                ldsm4(ah[mt], sb + QV_A + (uint32_t)((warp_m0 + mt * 16 + a_row) * QVR + ks * 32 + a_koff));
#pragma unroll
            for (int np = 0; np < 2; np++)
                ldsm4(b[np], sb + QV_BQ + (uint32_t)((warp_n0 + np * 16 + b_row) * QVR + ks * 32 + b_koff));
#pragma unroll
            for (int mt = 0; mt < 2; mt++)
#pragma unroll
                for (int nt = 0; nt < 4; nt++)
                    mma_f16(accq[mt][nt], ah[mt], &b[nt >> 1][(nt & 1) * 2]);
#pragma unroll
            for (int np = 0; np < 2; np++)
                ldsm4(b[np], sb + QV_BV + (uint32_t)((warp_n0 + np * 16 + b_row) * QVR + ks * 32 + b_koff));
#pragma unroll
            for (int mt = 0; mt < 2; mt++)
#pragma unroll
                for (int nt = 0; nt < 4; nt++)
                    mma_f16(accv[mt][nt], ah[mt], &b[nt >> 1][(nt & 1) * 2]);
        }
    }

    const int bb = m0 >> 11;
    const int s0 = m0 & 2047;
    const int h = n0 >> 6;
    const size_t base = ((size_t)(bb * H_ + h) * S_ + s0) * 64;

    // ---- Q epilogue ----
    __syncthreads();
#pragma unroll
    for (int mt = 0; mt < 2; mt++)
#pragma unroll
        for (int nt = 0; nt < 4; nt++) {
            int r = warp_m0 + mt * 16 + (lane >> 2);
            int c = warp_n0 + nt * 8 + (lane & 3) * 2;
            Cs[r * CSP + c]           = accq[mt][nt][0];
            Cs[r * CSP + c + 1]       = accq[mt][nt][1];
            Cs[(r + 8) * CSP + c]     = accq[mt][nt][2];
            Cs[(r + 8) * CSP + c + 1] = accq[mt][nt][3];
        }
    __syncthreads();
    for (int e = tid; e < 8192; e += 256) {
        int sl = e >> 6, d = e & 63;
        float x = Cs[sl * CSP + d] * SCALE_;
        __half hv = __float2half(x);
        g_Qh[base + (size_t)sl * 64 + d] = hv;
        g_Ql[base + (size_t)sl * 64 + d] = __float2half(x - __half2float(hv));
    }
    // ---- V epilogue ----
    __syncthreads();
#pragma unroll
    for (int mt = 0; mt < 2; mt++)
#pragma unroll
        for (int nt = 0; nt < 4; nt++) {
            int r = warp_m0 + mt * 16 + (lane >> 2);
            int c = warp_n0 + nt * 8 + (lane & 3) * 2;
            Cs[r * CSP + c]           = accv[mt][nt][0];
            Cs[r * CSP + c + 1]       = accv[mt][nt][1];
            Cs[(r + 8) * CSP + c]     = accv[mt][nt][2];
            Cs[(r + 8) * CSP + c + 1] = accv[mt][nt][3];
        }
    __syncthreads();
    for (int e = tid; e < 8192; e += 256) {
        int sl = e >> 6, d = e & 63;
        g_V[base + (size_t)sl * 64 + d] = __float2half(Cs[sl * CSP + d]);
    }
}

// ================= gemm_f16: mode 1 = K projection (3-term), mode 3 = out-proj (1-term) =================
#define G2R 144
#define G2_AH 0
#define G2_AL 18432
#define G2_BH 36864
#define G2_BL 46080
#define G2_STG 55296
#define GEMM2_SMEM 110592

__global__ void __launch_bounds__(256, 2)
gemm_f16(const __half* __restrict__ Ah, const __half* __restrict__ Al,
         const float* __restrict__ bias, float* __restrict__ outp, int mode) {
    extern __shared__ char smc[];
    const uint32_t smb = (uint32_t)__cvta_generic_to_shared(smc);
    float* Cs = (float*)smc;

    const int tid = threadIdx.x;
    const int wid = tid >> 5;
    const int lane = tid & 31;
    const int n0 = blockIdx.x * 64;
    const int m0 = blockIdx.y * 128;
    const bool kz = (mode == 1);
    const size_t woff = (size_t)(kz ? 1 : 3) * D_ * D_;

    const int warp_m0 = (wid & 3) * 32;
    const int warp_n0 = (wid >> 2) * 32;

    auto stage = [&](int ch) {
        uint32_t sb = smb + (uint32_t)(ch & 1) * G2_STG;
        const int K0 = ch * 64;
        const int na = kz ? 8 : 4;
        for (int i = 0; i < na; i++) {
            int e = tid + i * 256;
            int half_ = e >> 10, r = (e >> 3) & 127, c = e & 7;
            const __half* src = (half_ ? Al : Ah) + (size_t)(m0 + r) * D_ + K0 + c * 8;
            cp16(sb + (half_ ? G2_AL : G2_AH) + r * G2R + c * 16, src);
        }
        const int nb = kz ? 4 : 2;
        for (int i = 0; i < nb; i++) {
            int e = tid + i * 256;
            int half_ = e >> 9, n = (e >> 3) & 63, c = e & 7;
            const __half* src = (half_ ? g_Wktl : (g_Wt + woff)) +
                                (size_t)(n0 + n) * D_ + K0 + c * 8;
            cp16(sb + (half_ ? G2_BL : G2_BH) + n * G2R + c * 16, src);
        }
        cp_commit();
    };

    float acc[2][4][4] = {};

    const int lrm = lane & 7;
    const int lmat = lane >> 3;
    const int a_row = lrm + (lmat & 1) * 8;
    const int a_koff = (lmat >> 1) * 16;
    const int b_row = lrm + (lmat >> 1) * 8;
    const int b_koff = (lmat & 1) * 16;

    stage(0);
    for (int ch = 0; ch < 16; ch++) {
        cp_wait0();
        __syncthreads();
        if (ch + 1 < 16) stage(ch + 1);
        const uint32_t sb = smb + (uint32_t)(ch & 1) * G2_STG;

#pragma unroll
        for (int ks = 0; ks < 4; ks++) {
            uint32_t ah[2][4], al[2][4], bh[2][4], bl[2][4];
#pragma unroll
            for (int mt = 0; mt < 2; mt++) {
                uint32_t ad = sb + G2_AH + (uint32_t)((warp_m0 + mt * 16 + a_row) * G2R + ks * 32 + a_koff);
                ldsm4(ah[mt], ad);
                if (kz) ldsm4(al[mt], ad + (G2_AL - G2_AH));
            }
#pragma unroll
            for (int np = 0; np < 2; np++) {
                uint32_t ad = sb + G2_BH + (uint32_t)((warp_n0 + np * 16 + b_row) * G2R + ks * 32 + b_koff);
                ldsm4(bh[np], ad);
                if (kz) ldsm4(bl[np], ad + (G2_BL - G2_BH));
            }
#pragma unroll
            for (int mt = 0; mt < 2; mt++)
#pragma unroll
                for (int nt = 0; nt < 4; nt++)
                    mma_f16(acc[mt][nt], ah[mt], &bh[nt >> 1][(nt & 1) * 2]);
            if (kz) {
#pragma unroll
                for (int mt = 0; mt < 2; mt++)
#pragma unroll
                    for (int nt = 0; nt < 4; nt++)
                        mma_f16(acc[mt][nt], al[mt], &bh[nt >> 1][(nt & 1) * 2]);
#pragma unroll
                for (int mt = 0; mt < 2; mt++)
#pragma unroll
                    for (int nt = 0; nt < 4; nt++)
                        mma_f16(acc[mt][nt], ah[mt], &bl[nt >> 1][(nt & 1) * 2]);
            }
        }
    }

#pragma unroll
    for (int mt = 0; mt < 2; mt++)
#pragma unroll
        for (int nt = 0; nt < 4; nt++) {
            int r = warp_m0 + mt * 16 + (lane >> 2);
            int c = warp_n0 + nt * 8 + (lane & 3) * 2;
            Cs[r * CSP + c]           = acc[mt][nt][0];
            Cs[r * CSP + c + 1]       = acc[mt][nt][1];
            Cs[(r + 8) * CSP + c]     = acc[mt][nt][2];
            Cs[(r + 8) * CSP + c + 1] = acc[mt][nt][3];
        }
    __syncthreads();

    const int bb = m0 >> 11;
    const int s0 = m0 & 2047;
    const int h = n0 >> 6;
    if (!kz) {
        for (int e = tid; e < 8192; e += 256) {
            int sl = e >> 6, d = e & 63;
            outp[(size_t)(m0 + sl) * D_ + n0 + d] = Cs[sl * CSP + d] + bias[n0 + d];
        }
    } else {
        size_t base = ((size_t)(bb * H_ + h) * S_ + s0) * 64;
        for (int e = tid; e < 8192; e += 256) {
            int sl = e >> 6, d = e & 63;
            g_K[base + (size_t)sl * 64 + d] = __float2half(Cs[sl * CSP + d]);
        }
        if (tid < 128) {
            float s = 0.f;
#pragma unroll 8
            for (int c = 0; c < 64; c++) { float v = Cs[tid * CSP + c]; s += v * v; }
            g_knorm[(bb * H_ + h) * S_ + s0 + tid] = s;
        }
    }
}

// ---------------- top-k (radix select on exact fp32 norms) + gather ----------------
__global__ void __launch_bounds__(512) topk_gather() {
    __shared__ uint32_t bits[S_];
    __shared__ uint32_t hist[256];
    __shared__ int sel[256];
    __shared__ uint32_t bc[2];
    __shared__ uint32_t cnt, eqc;

    const int bh = blockIdx.x;
    const int tid = threadIdx.x;

    for (int s = tid; s < S_; s += 512)
        bits[s] = __float_as_uint(g_knorm[bh * S_ + s]);
    if (tid == 0) { cnt = 0; eqc = 0; }
    if (tid >= 204 && tid < 256) sel[tid] = -1;
    __syncthreads();

    uint32_t prefix = 0, pmask = 0, k_rem = NG_;
#pragma unroll
    for (int level = 3; level >= 0; level--) {
        const int sh = level * 8;
        if (tid < 256) hist[tid] = 0;
        __syncthreads();
        for (int s = tid; s < S_; s += 512) {
            uint32_t v = bits[s];
            if ((v & pmask) == prefix)
                atomicAdd(&hist[(v >> sh) & 255], 1u);
        }
        __syncthreads();
        if (tid < 32) {
            const int base = tid * 8;
            uint32_t tot = 0;
#pragma unroll
            for (int i = 0; i < 8; i++) tot += hist[base + i];
            uint32_t suf = tot;
#pragma unroll
            for (int off = 1; off < 32; off <<= 1) {
                uint32_t t = __shfl_down_sync(0xffffffffu, suf, off);
                if (tid + off < 32) suf += t;
            }
            uint32_t suf_excl = suf - tot;
            if (suf_excl < k_rem && k_rem <= suf) {
                uint32_t cum = suf_excl;
                for (int i = 7; i >= 0; i--) {
                    cum += hist[base + i];
                    if (cum >= k_rem) {
                        bc[0] = (uint32_t)(base + i);
                        bc[1] = k_rem - (cum - hist[base + i]);
                        break;
                    }
                }
            }
        }
        __syncthreads();
        prefix |= bc[0] << sh;
        pmask  |= 255u << sh;
        k_rem = bc[1];
        __syncthreads();
    }

    const uint32_t T = prefix;
    for (int s = tid; s < S_; s += 512) {
        uint32_t v = bits[s];
        if (v > T) {
            int p = atomicAdd(&cnt, 1u);
            sel[p] = s;
        } else if (v == T) {
            uint32_t e = atomicAdd(&eqc, 1u);
            if (e < k_rem) {
                int p = atomicAdd(&cnt, 1u);
                sel[p] = s;
            }
        }
    }
    __syncthreads();

    const size_t sb = (size_t)bh * S_ * 64;
    const size_t gb = (size_t)bh * 256 * 64;
    const uint4 zero = make_uint4(0, 0, 0, 0);
    for (int e = tid; e < 2048; e += 512) {
        int g = e >> 3, c = e & 7;
        int k = sel[g];
        size_t so = sb + (size_t)k * 64 + c * 8;
        size_t go = gb + (size_t)g * 64 + c * 8;
        *(uint4*)(g_Kg + go) = (k >= 0) ? *(const uint4*)(g_K + so) : zero;
        *(uint4*)(g_Vg + go) = (k >= 0) ? *(const uint4*)(g_V + so) : zero;
    }
}

// ================= flash attention (merged local z=0 / global z=1) =================
#define ROWQ 144
#define QH_OFF 0
#define QL_OFF 18432
#define KV0 36864
#define KVSZ 18432
#define KH_O 0
#define VH_O 9216
#define FLM_SMEM 73728

__global__ void __launch_bounds__(256, 2) flash_mma(
    const float* __restrict__ gamma, const float* __restrict__ beta) {
    extern __shared__ char smc[];
    const uint32_t smb = (uint32_t)__cvta_generic_to_shared(smc);
    const int tid = threadIdx.x;
    const int wid = tid >> 5;
    const int lane = tid & 31;
    const int bh = blockIdx.y;
    const int q0 = blockIdx.x * 128;
    const int z = blockIdx.z;

    const size_t kv_stride = z ? (size_t)256 * 64 : (size_t)S_ * 64;
    const int n_keys  = z ? NG_ : S_;
    const int n_tiles = z ? 4 : S_ / 64;
    const int cat_off = z ? 64 : 0;

    const __half* Qh = g_Qh + ((size_t)bh * S_ + q0) * 64;
    const __half* Ql = g_Ql + ((size_t)bh * S_ + q0) * 64;
    const __half* Kp = (z ? g_Kg : g_K) + (size_t)bh * kv_stride;
    const __half* Vp = (z ? g_Vg : g_V) + (size_t)bh * kv_stride;
    __half* cath = g_cath + ((size_t)bh * S_ + q0) * 128 + cat_off;

    const __half* srcs[2] = {Kp, Vp};
    auto stage_tile = [&](int t, int bsel) {
        uint32_t dstb = smb + KV0 + bsel * KVSZ;
#pragma unroll
        for (int i = 0; i < 4; i++) {
            int e = tid + i * 256;
            int arr = e >> 9, r = (e >> 3) & 63, c = e & 7;
            cp16(dstb + arr * 9216 + r * ROWQ + c * 16,
                 srcs[arr] + (size_t)(t * 64 + r) * 64 + c * 8);
        }
        cp_commit();
    };
    stage_tile(0, 0);

    for (int e = tid; e < 1024; e += 256) {
        int r = e >> 3, c = e & 7;
        *(uint4*)(smc + QH_OFF + r * ROWQ + c * 16) = *(const uint4*)(Qh + (size_t)r * 64 + c * 8);
        if (z)
            *(uint4*)(smc + QL_OFF + r * ROWQ + c * 16) = *(const uint4*)(Ql + (size_t)r * 64 + c * 8);
    }
    __syncthreads();

    const int lrm = lane & 7;
    const int lmat = lane >> 3;
    const int a_row = lrm + (lmat & 1) * 8;
    const int a_koff = (lmat >> 1) * 16;
    const int b_row = lrm + (lmat >> 1) * 8;
    const int b_koff = (lmat & 1) * 16;
    const int t_row = lrm + (lmat & 1) * 8;
    const int t_col = (lmat >> 1) * 8;
    const int wm = wid * 16;

    float o[8][4] = {};
    float m0 = -1e30f, m1 = -1e30f, l0 = 0.f, l1 = 0.f;

    for (int t = 0; t < n_tiles; t++) {
        cp_wait0();
        __syncthreads();
        if (t + 1 < n_tiles) stage_tile(t + 1, (t + 1) & 1);
        const uint32_t bb = smb + KV0 + (uint32_t)(t & 1) * KVSZ;

        float sc[8][4] = {};
#pragma unroll
        for (int ks = 0; ks < 4; ks++) {
            uint32_t aqh[4], aql[4];
            uint32_t qa = smb + QH_OFF + (uint32_t)((wm + a_row) * ROWQ + ks * 32 + a_koff);
            ldsm4(aqh, qa);
            if (z) ldsm4(aql, qa + (QL_OFF - QH_OFF));
            uint32_t kb[4][4];
#pragma unroll
            for (int np = 0; np < 4; np++)
                ldsm4(kb[np], bb + KH_O + (uint32_t)((np * 16 + b_row) * ROWQ + ks * 32 + b_koff));
#pragma unroll
            for (int np = 0; np < 4; np++)
#pragma unroll
                for (int hf = 0; hf < 2; hf++)
                    mma_f16(sc[np * 2 + hf], aqh, &kb[np][hf * 2]);
            if (z) {
#pragma unroll
                for (int np = 0; np < 4; np++)
#pragma unroll
                    for (int hf = 0; hf < 2; hf++)
                        mma_f16(sc[np * 2 + hf], aql, &kb[np][hf * 2]);
            }
        }

        if ((t + 1) * 64 > n_keys) {
            int cb2 = t * 64 + (lane & 3) * 2;
#pragma unroll
            for (int j = 0; j < 8; j++)
#pragma unroll
                for (int ii = 0; ii < 2; ii++) {
                    if (cb2 + j * 8 + ii >= n_keys) { sc[j][ii] = -1e30f; sc[j][2 + ii] = -1e30f; }
                }
        }

        float mx0 = -1e30f, mx1 = -1e30f;
#pragma unroll
        for (int j = 0; j < 8; j++) {
            mx0 = fmaxf(mx0, fmaxf(sc[j][0], sc[j][1]));
            mx1 = fmaxf(mx1, fmaxf(sc[j][2], sc[j][3]));
        }
        mx0 = fmaxf(mx0, __shfl_xor_sync(0xffffffffu, mx0, 1));
        mx0 = fmaxf(mx0, __shfl_xor_sync(0xffffffffu, mx0, 2));
        mx1 = fmaxf(mx1, __shfl_xor_sync(0xffffffffu, mx1, 1));
        mx1 = fmaxf(mx1, __shfl_xor_sync(0xffffffffu, mx1, 2));
        float mn0 = fmaxf(m0, mx0), mn1 = fmaxf(m1, mx1);
        float c0 = __expf(m0 - mn0), c1 = __expf(m1 - mn1);
        m0 = mn0; m1 = mn1;
        float s0 = 0.f, s1 = 0.f;
#pragma unroll
        for (int j = 0; j < 8; j++) {
            sc[j][0] = __expf(sc[j][0] - mn0); s0 += sc[j][0];
            sc[j][1] = __expf(sc[j][1] - mn0); s0 += sc[j][1];
            sc[j][2] = __expf(sc[j][2] - mn1); s1 += sc[j][2];
            sc[j][3] = __expf(sc[j][3] - mn1); s1 += sc[j][3];
        }
        s0 += __shfl_xor_sync(0xffffffffu, s0, 1);
        s0 += __shfl_xor_sync(0xffffffffu, s0, 2);
        s1 += __shfl_xor_sync(0xffffffffu, s1, 1);
        s1 += __shfl_xor_sync(0xffffffffu, s1, 2);
        l0 = l0 * c0 + s0;
        l1 = l1 * c1 + s1;
#pragma unroll
        for (int j = 0; j < 8; j++) {
            o[j][0] *= c0; o[j][1] *= c0; o[j][2] *= c1; o[j][3] *= c1;
        }

#pragma unroll
        for (int ks = 0; ks < 4; ks++) {
            uint32_t pah[4], pal[4];
            if (z) {
                split2h(sc[2 * ks][0],     sc[2 * ks][1],     pah[0], pal[0]);
                split2h(sc[2 * ks][2],     sc[2 * ks][3],     pah[1], pal[1]);
                split2h(sc[2 * ks + 1][0], sc[2 * ks + 1][1], pah[2], pal[2]);
                split2h(sc[2 * ks + 1][2], sc[2 * ks + 1][3], pah[3], pal[3]);
            } else {
                pah[0] = pack2h(sc[2 * ks][0],     sc[2 * ks][1]);
                pah[1] = pack2h(sc[2 * ks][2],     sc[2 * ks][3]);
                pah[2] = pack2h(sc[2 * ks + 1][0], sc[2 * ks + 1][1]);
                pah[3] = pack2h(sc[2 * ks + 1][2], sc[2 * ks + 1][3]);
            }
#pragma unroll
            for (int dq = 0; dq < 2; dq++) {
                uint32_t vb[2][4];
#pragma unroll
                for (int p = 0; p < 2; p++) {
                    int dp = dq * 2 + p;
                    ldsm4t(vb[p], bb + VH_O + (uint32_t)((ks * 16 + t_row) * ROWQ + (dp * 16 + t_col) * 2));
                }
#pragma unroll
                for (int p = 0; p < 2; p++) {
                    int dp = dq * 2 + p;
                    mma_f16(o[dp * 2],     pah, &vb[p][0]);
                    mma_f16(o[dp * 2 + 1], pah, &vb[p][2]);
                }
                if (z) {
#pragma unroll
                    for (int p = 0; p < 2; p++) {
                        int dp = dq * 2 + p;
                        mma_f16(o[dp * 2],     pal, &vb[p][0]);
                        mma_f16(o[dp * 2 + 1], pal, &vb[p][2]);
                    }
                }
            }
        }
    }

    // ---- epilogue: single-fp16 cat writes ----
    const float inv0 = 1.f / l0, inv1 = 1.f / l1;
    const int rq = wm + (lane >> 2);
    const int cb = (lane & 3) * 2;
    float v0[8][2], v1[8][2];
#pragma unroll
    for (int j = 0; j < 8; j++) {
        v0[j][0] = o[j][0] * inv0; v0[j][1] = o[j][1] * inv0;
        v1[j][0] = o[j][2] * inv1; v1[j][1] = o[j][3] * inv1;
    }
    if (z) {
        float sum0 = 0.f, sum1 = 0.f;
#pragma unroll
        for (int j = 0; j < 8; j++) {
            sum0 += v0[j][0] + v0[j][1];
            sum1 += v1[j][0] + v1[j][1];
        }
        sum0 += __shfl_xor_sync(0xffffffffu, sum0, 1);
        sum0 += __shfl_xor_sync(0xffffffffu, sum0, 2);
        sum1 += __shfl_xor_sync(0xffffffffu, sum1, 1);
        sum1 += __shfl_xor_sync(0xffffffffu, sum1, 2);
        float mu0 = sum0 * (1.f / 64.f), mu1 = sum1 * (1.f / 64.f);
        float var0 = 0.f, var1 = 0.f;
#pragma unroll
        for (int j = 0; j < 8; j++) {
            float a0 = v0[j][0] - mu0, a1 = v0[j][1] - mu0;
            float b0 = v1[j][0] - mu1, b1 = v1[j][1] - mu1;
            var0 += a0 * a0 + a1 * a1;
            var1 += b0 * b0 + b1 * b1;
        }
        var0 += __shfl_xor_sync(0xffffffffu, var0, 1);
        var0 += __shfl_xor_sync(0xffffffffu, var0, 2);
        var1 += __shfl_xor_sync(0xffffffffu, var1, 1);
        var1 += __shfl_xor_sync(0xffffffffu, var1, 2);
        float is0 = rsqrtf(var0 * (1.f / 64.f) + 1e-5f);
        float is1 = rsqrtf(var1 * (1.f / 64.f) + 1e-5f);
#pragma unroll
        for (int j = 0; j < 8; j++) {
            int col = j * 8 + cb;
            float g0 = gamma[col], g1 = gamma[col + 1];
            float be0 = beta[col], be1 = beta[col + 1];
            v0[j][0] = (v0[j][0] - mu0) * is0 * g0 + be0;
            v0[j][1] = (v0[j][1] - mu0) * is0 * g1 + be1;
            v1[j][0] = (v1[j][0] - mu1) * is1 * g0 + be0;
            v1[j][1] = (v1[j][1] - mu1) * is1 * g1 + be1;
        }
    }
#pragma unroll
    for (int j = 0; j < 8; j++) {
        int col = j * 8 + cb;
        *(uint32_t*)(cath + (size_t)rq * 128 + col)       = pack2h(v0[j][0], v0[j][1]);
        *(uint32_t*)(cath + (size_t)(rq + 8) * 128 + col) = pack2h(v1[j][0], v1[j][1]);
    }
}

// ================= gate via mma (single-term; single-fp16 cat) =================
#define GR 272
#define GA 0
#define GB 34816
#define GATE_SMEM 52224

__global__ void __launch_bounds__(256, 2)
gate_mma(const float* __restrict__ bg) {
    extern __shared__ char smc[];
    const uint32_t smb = (uint32_t)__cvta_generic_to_shared(smc);
    const int tid = threadIdx.x;
    const int wid = tid >> 5;
    const int lane = tid & 31;
    const int m0 = blockIdx.x * 128;

#pragma unroll
    for (int i = 0; i < 8; i++) {
        int e = tid + i * 256;
        int r = e >> 4, c = e & 15;
        cp16(smb + GA + r * GR + c * 16, g_cath + (size_t)(m0 + r) * 128 + c * 8);
    }
#pragma unroll
    for (int i = 0; i < 4; i++) {
        int e = tid + i * 256;
        int r = (e >> 4) & 63, c = e & 15;
        cp16(smb + GB + r * GR + c * 16, g_Wgt + (size_t)r * 128 + c * 8);
    }
    cp_commit();
    cp_wait0();
    __syncthreads();

    const int lrm = lane & 7;
    const int lmat = lane >> 3;
    const int a_row = lrm + (lmat & 1) * 8;
    const int a_koff = (lmat >> 1) * 16;
    const int b_row = lrm + (lmat >> 1) * 8;
    const int b_koff = (lmat & 1) * 16;
    const int wm = wid * 16;

    float acc[8][4] = {};
#pragma unroll
    for (int ks = 0; ks < 8; ks++) {
        uint32_t ah[4];
        ldsm4(ah, smb + GA + (uint32_t)((wm + a_row) * GR + ks * 32 + a_koff));
        uint32_t b[4][4];
#pragma unroll
        for (int np = 0; np < 4; np++)
            ldsm4(b[np], smb + GB + (uint32_t)((np * 16 + b_row) * GR + ks * 32 + b_koff));
#pragma unroll
        for (int np = 0; np < 4; np++)
#pragma unroll
            for (int hf = 0; hf < 2; hf++)
                mma_f16(acc[np * 2 + hf], ah, &b[np][hf * 2]);
    }

    const int rq = wm + (lane >> 2);
    const int cb = (lane & 3) * 2;
#pragma unroll
    for (int rr = 0; rr < 2; rr++) {
        const int r = rq + rr * 8;
        const int R = m0 + r;
        const int bh = R >> 11;
        const int ss = R & 2047;
        const size_t obase = ((size_t)((bh >> 4) * S_ + ss)) * D_ + (bh & 15) * 64;
#pragma unroll
        for (int j = 0; j < 8; j++) {
            const int col = j * 8 + cb;
            float z0 = acc[j][rr * 2 + 0] + bg[col];
            float z1 = acc[j][rr * 2 + 1] + bg[col + 1];
            float g0 = 1.f / (1.f + __expf(-z0));
            float g1 = 1.f / (1.f + __expf(-z1));
            uint32_t lh = *(uint32_t*)(smc + GA + r * GR + col * 2);
            uint32_t gh = *(uint32_t*)(smc + GA + r * GR + (64 + col) * 2);
            float2 lh2 = __half22float2(*(__half2*)&lh);
            float2 gh2 = __half22float2(*(__half2*)&gh);
            float f0 = g0 * lh2.x + (1.f - g0) * gh2.x;
            float f1 = g1 * lh2.y + (1.f - g1) * gh2.y;
            *(uint32_t*)(g_Fh + obase + col) = pack2h(f0, f1);
        }
    }
}

// ---------------- launch ----------------
extern "C" void kernel_launch(void* const* d_in, const int* in_sizes, int n_in,
                              void* d_out, int out_size) {
    (void)in_sizes; (void)n_in; (void)out_size;
    const float* x   = (const float*)d_in[0];
    const float* Wq  = (const float*)d_in[1];
    const float* Wk  = (const float*)d_in[2];
    const float* Wv  = (const float*)d_in[3];
    const float* Wo  = (const float*)d_in[4];
    const float* bo  = (const float*)d_in[5];
    const float* gam = (const float*)d_in[6];
    const float* bet = (const float*)d_in[7];
    const float* Wg  = (const float*)d_in[8];
    const float* bg  = (const float*)d_in[9];
    float* out = (float*)d_out;

    cudaFuncSetAttribute(gemm_qv,   cudaFuncAttributeMaxDynamicSharedMemorySize, QV_SMEM);
    cudaFuncSetAttribute(gemm_f16,  cudaFuncAttributeMaxDynamicSharedMemorySize, GEMM2_SMEM);
    cudaFuncSetAttribute(flash_mma, cudaFuncAttributeMaxDynamicSharedMemorySize, FLM_SMEM);
    cudaFuncSetAttribute(gate_mma,  cudaFuncAttributeMaxDynamicSharedMemorySize, GATE_SMEM);

    __half *xh, *xl, *fh;
    cudaGetSymbolAddress((void**)&xh, g_Xh);
    cudaGetSymbolAddress((void**)&xl, g_Xl);
    cudaGetSymbolAddress((void**)&fh, g_Fh);

    conv_x<<<(B_ * S_ * D_) / 1024, 256>>>(x);
    conv_wt<<<dim3(32, 32, 4), dim3(32, 8)>>>(Wq, Wk, Wv, Wo);
    conv_wg<<<32, 256>>>(Wg);
    gemm_qv<<<dim3(16, 32), 256, QV_SMEM>>>();
    gemm_f16<<<dim3(16, 32), 256, GEMM2_SMEM>>>(xh, xl, nullptr, nullptr, 1);
    topk_gather<<<B_ * H_, 512>>>();
    flash_mma<<<dim3(S_ / 128, B_ * H_, 2), 256, FLM_SMEM>>>(gam, bet);
    gate_mma<<<(B_ * H_ * S_) / 128, 256, GATE_SMEM>>>(bg);
    gemm_f16<<<dim3(16, 32), 256, GEMM2_SMEM>>>(fh, fh, bo, out, 3);
}

// round 17
// speedup vs baseline: 1.5224x; 1.5224x over previous
#include <cuda_runtime.h>
#include <cuda_fp16.h>
#include <cstdint>

#define B_ 2
#define S_ 2048
#define D_ 1024
#define H_ 16
#define DH_ 64
#define NG_ 204
#define SCALE_ 0.125f

// ---------------- scratch (static device globals; no allocations) ----------------
__device__ __half g_Qh[B_ * H_ * S_ * DH_];   // [bh][s][d], pre-scaled by SCALE_
__device__ __half g_Ql[B_ * H_ * S_ * DH_];
__device__ __half g_K [B_ * H_ * S_ * DH_];
__device__ __half g_V [B_ * H_ * S_ * DH_];
__device__ __half g_Kg[B_ * H_ * 256 * DH_];
__device__ __half g_Vg[B_ * H_ * 256 * DH_];
__device__ __half g_Xh[B_ * S_ * D_];
__device__ __half g_Xl[B_ * S_ * D_];         // lo used only by K projection
__device__ __half g_Fh[B_ * S_ * D_];         // fused (gate output), single fp16
__device__ __half g_Wt[4 * D_ * D_];          // W^T [z][n][k] single fp16
__device__ __half g_Wktl[D_ * D_];            // Wk^T lo (K projection 3-term)
__device__ __half g_Wgt[128 * 64];            // Wg^T
__device__ __half g_cath[(size_t)B_ * H_ * S_ * 128];  // [row][local 64 | global 64]
__device__ float  g_knorm[B_ * H_ * S_];      // exact fp32 squared key norms

// ================= mma.sync helpers =================
__device__ __forceinline__ void mma_f16(float* c, const uint32_t* a, const uint32_t* b) {
    asm volatile(
        "mma.sync.aligned.m16n8k16.row.col.f32.f16.f16.f32 "
        "{%0,%1,%2,%3}, {%4,%5,%6,%7}, {%8,%9}, {%0,%1,%2,%3};"
        : "+f"(c[0]), "+f"(c[1]), "+f"(c[2]), "+f"(c[3])
        : "r"(a[0]), "r"(a[1]), "r"(a[2]), "r"(a[3]), "r"(b[0]), "r"(b[1]));
}
__device__ __forceinline__ void ldsm4(uint32_t* r, uint32_t addr) {
    asm volatile("ldmatrix.sync.aligned.m8n8.x4.shared.b16 {%0,%1,%2,%3}, [%4];"
                 : "=r"(r[0]), "=r"(r[1]), "=r"(r[2]), "=r"(r[3]) : "r"(addr));
}
__device__ __forceinline__ void ldsm4t(uint32_t* r, uint32_t addr) {
    asm volatile("ldmatrix.sync.aligned.m8n8.x4.trans.shared.b16 {%0,%1,%2,%3}, [%4];"
                 : "=r"(r[0]), "=r"(r[1]), "=r"(r[2]), "=r"(r[3]) : "r"(addr));
}
__device__ __forceinline__ void cp16(uint32_t dst, const void* src) {
    asm volatile("cp.async.cg.shared.global [%0], [%1], 16;" :: "r"(dst), "l"(src));
}
__device__ __forceinline__ void cp_commit() { asm volatile("cp.async.commit_group;"); }
__device__ __forceinline__ void cp_wait0()  { asm volatile("cp.async.wait_group 0;"); }

__device__ __forceinline__ void split2h(float x0, float x1, uint32_t& hi, uint32_t& lo) {
    __half h0 = __float2half(x0);
    __half h1 = __float2half(x1);
    float r0 = x0 - __half2float(h0);
    float r1 = x1 - __half2float(h1);
    __half2 Hh = __halves2half2(h0, h1);
    __half2 Ll = __halves2half2(__float2half(r0), __float2half(r1));
    hi = *reinterpret_cast<uint32_t*>(&Hh);
    lo = *reinterpret_cast<uint32_t*>(&Ll);
}
__device__ __forceinline__ uint32_t pack2h(float x0, float x1) {
    __half2 h = __halves2half2(__float2half(x0), __float2half(x1));
    return *reinterpret_cast<uint32_t*>(&h);
}

// ================= pre-conversion kernels =================
__global__ void conv_x(const float* __restrict__ x) {
    int idx = blockIdx.x * 256 + threadIdx.x;
    float4 v = *(const float4*)(x + (size_t)idx * 4);
    uint32_t h0, l0, h1, l1;
    split2h(v.x, v.y, h0, l0);
    split2h(v.z, v.w, h1, l1);
    *(uint2*)(g_Xh + (size_t)idx * 4) = make_uint2(h0, h1);
    *(uint2*)(g_Xl + (size_t)idx * 4) = make_uint2(l0, l1);
}

__global__ void conv_wt(const float* __restrict__ W0, const float* __restrict__ W1,
                        const float* __restrict__ W2, const float* __restrict__ W3) {
    __shared__ float t[32][33];
    const int z = blockIdx.z;
    const float* W = (z == 0) ? W0 : (z == 1) ? W1 : (z == 2) ? W2 : W3;
    const int n0 = blockIdx.x * 32, k0 = blockIdx.y * 32;
    const int tx = threadIdx.x, ty = threadIdx.y;
#pragma unroll
    for (int i = 0; i < 4; i++)
        t[ty + i * 8][tx] = W[(size_t)(k0 + ty + i * 8) * D_ + n0 + tx];
    __syncthreads();
    size_t ob = (size_t)z * D_ * D_;
#pragma unroll
    for (int i = 0; i < 4; i++) {
        float v = t[tx][ty + i * 8];
        __half h = __float2half(v);
        size_t o = (size_t)(n0 + ty + i * 8) * D_ + k0 + tx;
        g_Wt[ob + o] = h;
        if (z == 1) g_Wktl[o] = __float2half(v - __half2float(h));
    }
}

__global__ void conv_wg(const float* __restrict__ Wg) {
    int t = blockIdx.x * 256 + threadIdx.x;
    int k = t >> 6, n = t & 63;
    g_Wgt[n * 128 + k] = __float2half(Wg[t]);
}

// ================= fp16 mma GEMM (R14 structure: one 3-z launch) =================
// Terms: K proj (z==1): 3-term — protects top-k. Q, V, out-proj: 1-term.
#define G2R 144
#define G2_AH 0
#define G2_AL 18432
#define G2_BH 36864
#define G2_BL 46080
#define G2_STG 55296
#define GEMM2_SMEM 110592
#define CSP 66

__global__ void __launch_bounds__(256, 2)
gemm_f16(const __half* __restrict__ Ah, const __half* __restrict__ Al,
         const float* __restrict__ bias, float* __restrict__ outp, int is_out) {
    extern __shared__ char smc[];
    const uint32_t smb = (uint32_t)__cvta_generic_to_shared(smc);
    float* Cs = (float*)smc;

    const int tid = threadIdx.x;
    const int wid = tid >> 5;
    const int lane = tid & 31;
    const int n0 = blockIdx.x * 64;
    const int m0 = blockIdx.y * 128;
    const int z = blockIdx.z;
    const bool kz = (!is_out) && (z == 1);
    const size_t woff = (size_t)(is_out ? 3 : z) * D_ * D_;

    const int warp_m0 = (wid & 3) * 32;
    const int warp_n0 = (wid >> 2) * 32;

    auto stage = [&](int ch) {
        uint32_t sb = smb + (uint32_t)(ch & 1) * G2_STG;
        const int K0 = ch * 64;
        const int na = kz ? 8 : 4;
        for (int i = 0; i < na; i++) {
            int e = tid + i * 256;
            int half_ = e >> 10, r = (e >> 3) & 127, c = e & 7;
            const __half* src = (half_ ? Al : Ah) + (size_t)(m0 + r) * D_ + K0 + c * 8;
            cp16(sb + (half_ ? G2_AL : G2_AH) + r * G2R + c * 16, src);
        }
        const int nb = kz ? 4 : 2;
        for (int i = 0; i < nb; i++) {
            int e = tid + i * 256;
            int half_ = e >> 9, n = (e >> 3) & 63, c = e & 7;
            const __half* src = (half_ ? g_Wktl : (g_Wt + woff)) +
                                (size_t)(n0 + n) * D_ + K0 + c * 8;
            cp16(sb + (half_ ? G2_BL : G2_BH) + n * G2R + c * 16, src);
        }
        cp_commit();
    };

    float acc[2][4][4] = {};

    const int lrm = lane & 7;
    const int lmat = lane >> 3;
    const int a_row = lrm + (lmat & 1) * 8;
    const int a_koff = (lmat >> 1) * 16;
    const int b_row = lrm + (lmat >> 1) * 8;
    const int b_koff = (lmat & 1) * 16;

    stage(0);
    for (int ch = 0; ch < 16; ch++) {
        cp_wait0();
        __syncthreads();
        if (ch + 1 < 16) stage(ch + 1);
        const uint32_t sb = smb + (uint32_t)(ch & 1) * G2_STG;

#pragma unroll
        for (int ks = 0; ks < 4; ks++) {
            uint32_t ah[2][4], al[2][4], bh[2][4], bl[2][4];
#pragma unroll
            for (int mt = 0; mt < 2; mt++) {
                uint32_t ad = sb + G2_AH + (uint32_t)((warp_m0 + mt * 16 + a_row) * G2R + ks * 32 + a_koff);
                ldsm4(ah[mt], ad);
                if (kz) ldsm4(al[mt], ad + (G2_AL - G2_AH));
            }
#pragma unroll
            for (int np = 0; np < 2; np++) {
                uint32_t ad = sb + G2_BH + (uint32_t)((warp_n0 + np * 16 + b_row) * G2R + ks * 32 + b_koff);
                ldsm4(bh[np], ad);
                if (kz) ldsm4(bl[np], ad + (G2_BL - G2_BH));
            }
#pragma unroll
            for (int mt = 0; mt < 2; mt++)
#pragma unroll
                for (int nt = 0; nt < 4; nt++)
                    mma_f16(acc[mt][nt], ah[mt], &bh[nt >> 1][(nt & 1) * 2]);
            if (kz) {
#pragma unroll
                for (int mt = 0; mt < 2; mt++)
#pragma unroll
                    for (int nt = 0; nt < 4; nt++)
                        mma_f16(acc[mt][nt], al[mt], &bh[nt >> 1][(nt & 1) * 2]);
#pragma unroll
                for (int mt = 0; mt < 2; mt++)
#pragma unroll
                    for (int nt = 0; nt < 4; nt++)
                        mma_f16(acc[mt][nt], ah[mt], &bl[nt >> 1][(nt & 1) * 2]);
            }
        }
    }

#pragma unroll
    for (int mt = 0; mt < 2; mt++)
#pragma unroll
        for (int nt = 0; nt < 4; nt++) {
            int r = warp_m0 + mt * 16 + (lane >> 2);
            int c = warp_n0 + nt * 8 + (lane & 3) * 2;
            Cs[r * CSP + c]           = acc[mt][nt][0];
            Cs[r * CSP + c + 1]       = acc[mt][nt][1];
            Cs[(r + 8) * CSP + c]     = acc[mt][nt][2];
            Cs[(r + 8) * CSP + c + 1] = acc[mt][nt][3];
        }
    __syncthreads();

    const int bb = m0 >> 11;
    const int s0 = m0 & 2047;
    const int h = n0 >> 6;
    if (is_out) {
        for (int e = tid; e < 8192; e += 256) {
            int sl = e >> 6, d = e & 63;
            outp[(size_t)(m0 + sl) * D_ + n0 + d] = Cs[sl * CSP + d] + bias[n0 + d];
        }
    } else if (z == 0) {
        size_t base = ((size_t)(bb * H_ + h) * S_ + s0) * 64;
        for (int e = tid; e < 8192; e += 256) {
            int sl = e >> 6, d = e & 63;
            float x = Cs[sl * CSP + d] * SCALE_;
            __half hv = __float2half(x);
            g_Qh[base + (size_t)sl * 64 + d] = hv;
            g_Ql[base + (size_t)sl * 64 + d] = __float2half(x - __half2float(hv));
        }
    } else {
        __half* dst = (z == 1) ? g_K : g_V;
        size_t base = ((size_t)(bb * H_ + h) * S_ + s0) * 64;
        for (int e = tid; e < 8192; e += 256) {
            int sl = e >> 6, d = e & 63;
            dst[base + (size_t)sl * 64 + d] = __float2half(Cs[sl * CSP + d]);
        }
        if (z == 1 && tid < 128) {
            float s = 0.f;
#pragma unroll 8
            for (int c = 0; c < 64; c++) { float v = Cs[tid * CSP + c]; s += v * v; }
            g_knorm[(bb * H_ + h) * S_ + s0 + tid] = s;
        }
    }
}

// ---------------- top-k (radix select on exact fp32 norms) + gather ----------------
__global__ void __launch_bounds__(512) topk_gather() {
    __shared__ uint32_t bits[S_];
    __shared__ uint32_t hist[256];
    __shared__ int sel[256];
    __shared__ uint32_t bc[2];
    __shared__ uint32_t cnt, eqc;

    const int bh = blockIdx.x;
    const int tid = threadIdx.x;

    for (int s = tid; s < S_; s += 512)
        bits[s] = __float_as_uint(g_knorm[bh * S_ + s]);
    if (tid == 0) { cnt = 0; eqc = 0; }
    if (tid >= 204 && tid < 256) sel[tid] = -1;
    __syncthreads();

    uint32_t prefix = 0, pmask = 0, k_rem = NG_;
#pragma unroll
    for (int level = 3; level >= 0; level--) {
        const int sh = level * 8;
        if (tid < 256) hist[tid] = 0;
        __syncthreads();
        for (int s = tid; s < S_; s += 512) {
            uint32_t v = bits[s];
            if ((v & pmask) == prefix)
                atomicAdd(&hist[(v >> sh) & 255], 1u);
        }
        __syncthreads();
        if (tid < 32) {
            const int base = tid * 8;
            uint32_t tot = 0;
#pragma unroll
            for (int i = 0; i < 8; i++) tot += hist[base + i];
            uint32_t suf = tot;
#pragma unroll
            for (int off = 1; off < 32; off <<= 1) {
                uint32_t t = __shfl_down_sync(0xffffffffu, suf, off);
                if (tid + off < 32) suf += t;
            }
            uint32_t suf_excl = suf - tot;
            if (suf_excl < k_rem && k_rem <= suf) {
                uint32_t cum = suf_excl;
                for (int i = 7; i >= 0; i--) {
                    cum += hist[base + i];
                    if (cum >= k_rem) {
                        bc[0] = (uint32_t)(base + i);
                        bc[1] = k_rem - (cum - hist[base + i]);
                        break;
                    }
                }
            }
        }
        __syncthreads();
        prefix |= bc[0] << sh;
        pmask  |= 255u << sh;
        k_rem = bc[1];
        __syncthreads();
    }

    const uint32_t T = prefix;
    for (int s = tid; s < S_; s += 512) {
        uint32_t v = bits[s];
        if (v > T) {
            int p = atomicAdd(&cnt, 1u);
            sel[p] = s;
        } else if (v == T) {
            uint32_t e = atomicAdd(&eqc, 1u);
            if (e < k_rem) {
                int p = atomicAdd(&cnt, 1u);
                sel[p] = s;
            }
        }
    }
    __syncthreads();

    const size_t sb = (size_t)bh * S_ * 64;
    const size_t gb = (size_t)bh * 256 * 64;
    const uint4 zero = make_uint4(0, 0, 0, 0);
    for (int e = tid; e < 2048; e += 512) {
        int g = e >> 3, c = e & 7;
        int k = sel[g];
        size_t so = sb + (size_t)k * 64 + c * 8;
        size_t go = gb + (size_t)g * 64 + c * 8;
        *(uint4*)(g_Kg + go) = (k >= 0) ? *(const uint4*)(g_K + so) : zero;
        *(uint4*)(g_Vg + go) = (k >= 0) ? *(const uint4*)(g_V + so) : zero;
    }
}

// ================= flash attention (merged local z=0 / global z=1) =================
#define ROWQ 144
#define QH_OFF 0
#define QL_OFF 18432
#define KV0 36864
#define KVSZ 18432
#define KH_O 0
#define VH_O 9216
#define FLM_SMEM 73728

__global__ void __launch_bounds__(256, 2) flash_mma(
    const float* __restrict__ gamma, const float* __restrict__ beta) {
    extern __shared__ char smc[];
    const uint32_t smb = (uint32_t)__cvta_generic_to_shared(smc);
    const int tid = threadIdx.x;
    const int wid = tid >> 5;
    const int lane = tid & 31;
    const int bh = blockIdx.y;
    const int q0 = blockIdx.x * 128;
    const int z = blockIdx.z;

    const size_t kv_stride = z ? (size_t)256 * 64 : (size_t)S_ * 64;
    const int n_keys  = z ? NG_ : S_;
    const int n_tiles = z ? 4 : S_ / 64;
    const int cat_off = z ? 64 : 0;

    const __half* Qh = g_Qh + ((size_t)bh * S_ + q0) * 64;
    const __half* Ql = g_Ql + ((size_t)bh * S_ + q0) * 64;
    const __half* Kp = (z ? g_Kg : g_K) + (size_t)bh * kv_stride;
    const __half* Vp = (z ? g_Vg : g_V) + (size_t)bh * kv_stride;
    __half* cath = g_cath + ((size_t)bh * S_ + q0) * 128 + cat_off;

    const __half* srcs[2] = {Kp, Vp};
    auto stage_tile = [&](int t, int bsel) {
        uint32_t dstb = smb + KV0 + bsel * KVSZ;
#pragma unroll
        for (int i = 0; i < 4; i++) {
            int e = tid + i * 256;
            int arr = e >> 9, r = (e >> 3) & 63, c = e & 7;
            cp16(dstb + arr * 9216 + r * ROWQ + c * 16,
                 srcs[arr] + (size_t)(t * 64 + r) * 64 + c * 8);
        }
        cp_commit();
    };
    stage_tile(0, 0);

    for (int e = tid; e < 1024; e += 256) {
        int r = e >> 3, c = e & 7;
        *(uint4*)(smc + QH_OFF + r * ROWQ + c * 16) = *(const uint4*)(Qh + (size_t)r * 64 + c * 8);
        if (z)
            *(uint4*)(smc + QL_OFF + r * ROWQ + c * 16) = *(const uint4*)(Ql + (size_t)r * 64 + c * 8);
    }
    __syncthreads();

    const int lrm = lane & 7;
    const int lmat = lane >> 3;
    const int a_row = lrm + (lmat & 1) * 8;
    const int a_koff = (lmat >> 1) * 16;
    const int b_row = lrm + (lmat >> 1) * 8;
    const int b_koff = (lmat & 1) * 16;
    const int t_row = lrm + (lmat & 1) * 8;
    const int t_col = (lmat >> 1) * 8;
    const int wm = wid * 16;

    float o[8][4] = {};
    float m0 = -1e30f, m1 = -1e30f, l0 = 0.f, l1 = 0.f;

    for (int t = 0; t < n_tiles; t++) {
        cp_wait0();
        __syncthreads();
        if (t + 1 < n_tiles) stage_tile(t + 1, (t + 1) & 1);
        const uint32_t bb = smb + KV0 + (uint32_t)(t & 1) * KVSZ;

        float sc[8][4] = {};
#pragma unroll
        for (int ks = 0; ks < 4; ks++) {
            uint32_t aqh[4], aql[4];
            uint32_t qa = smb + QH_OFF + (uint32_t)((wm + a_row) * ROWQ + ks * 32 + a_koff);
            ldsm4(aqh, qa);
            if (z) ldsm4(aql, qa + (QL_OFF - QH_OFF));
            uint32_t kb[4][4];
#pragma unroll
            for (int np = 0; np < 4; np++)
                ldsm4(kb[np], bb + KH_O + (uint32_t)((np * 16 + b_row) * ROWQ + ks * 32 + b_koff));
#pragma unroll
            for (int np = 0; np < 4; np++)
#pragma unroll
                for (int hf = 0; hf < 2; hf++)
                    mma_f16(sc[np * 2 + hf], aqh, &kb[np][hf * 2]);
            if (z) {
#pragma unroll
                for (int np = 0; np < 4; np++)
#pragma unroll
                    for (int hf = 0; hf < 2; hf++)
                        mma_f16(sc[np * 2 + hf], aql, &kb[np][hf * 2]);
            }
        }

        if ((t + 1) * 64 > n_keys) {
            int cb2 = t * 64 + (lane & 3) * 2;
#pragma unroll
            for (int j = 0; j < 8; j++)
#pragma unroll
                for (int ii = 0; ii < 2; ii++) {
                    if (cb2 + j * 8 + ii >= n_keys) { sc[j][ii] = -1e30f; sc[j][2 + ii] = -1e30f; }
                }
        }

        float mx0 = -1e30f, mx1 = -1e30f;
#pragma unroll
        for (int j = 0; j < 8; j++) {
            mx0 = fmaxf(mx0, fmaxf(sc[j][0], sc[j][1]));
            mx1 = fmaxf(mx1, fmaxf(sc[j][2], sc[j][3]));
        }
        mx0 = fmaxf(mx0, __shfl_xor_sync(0xffffffffu, mx0, 1));
        mx0 = fmaxf(mx0, __shfl_xor_sync(0xffffffffu, mx0, 2));
        mx1 = fmaxf(mx1, __shfl_xor_sync(0xffffffffu, mx1, 1));
        mx1 = fmaxf(mx1, __shfl_xor_sync(0xffffffffu, mx1, 2));
        float mn0 = fmaxf(m0, mx0), mn1 = fmaxf(m1, mx1);
        float c0 = __expf(m0 - mn0), c1 = __expf(m1 - mn1);
        m0 = mn0; m1 = mn1;
        float s0 = 0.f, s1 = 0.f;
#pragma unroll
        for (int j = 0; j < 8; j++) {
            sc[j][0] = __expf(sc[j][0] - mn0); s0 += sc[j][0];
            sc[j][1] = __expf(sc[j][1] - mn0); s0 += sc[j][1];
            sc[j][2] = __expf(sc[j][2] - mn1); s1 += sc[j][2];
            sc[j][3] = __expf(sc[j][3] - mn1); s1 += sc[j][3];
        }
        s0 += __shfl_xor_sync(0xffffffffu, s0, 1);
        s0 += __shfl_xor_sync(0xffffffffu, s0, 2);
        s1 += __shfl_xor_sync(0xffffffffu, s1, 1);
        s1 += __shfl_xor_sync(0xffffffffu, s1, 2);
        l0 = l0 * c0 + s0;
        l1 = l1 * c1 + s1;
#pragma unroll
        for (int j = 0; j < 8; j++) {
            o[j][0] *= c0; o[j][1] *= c0; o[j][2] *= c1; o[j][3] *= c1;
        }

#pragma unroll
        for (int ks = 0; ks < 4; ks++) {
            uint32_t pah[4], pal[4];
            if (z) {
                split2h(sc[2 * ks][0],     sc[2 * ks][1],     pah[0], pal[0]);
                split2h(sc[2 * ks][2],     sc[2 * ks][3],     pah[1], pal[1]);
                split2h(sc[2 * ks + 1][0], sc[2 * ks + 1][1], pah[2], pal[2]);
                split2h(sc[2 * ks + 1][2], sc[2 * ks + 1][3], pah[3], pal[3]);
            } else {
                pah[0] = pack2h(sc[2 * ks][0],     sc[2 * ks][1]);
                pah[1] = pack2h(sc[2 * ks][2],     sc[2 * ks][3]);
                pah[2] = pack2h(sc[2 * ks + 1][0], sc[2 * ks + 1][1]);
                pah[3] = pack2h(sc[2 * ks + 1][2], sc[2 * ks + 1][3]);
            }
#pragma unroll
            for (int dq = 0; dq < 2; dq++) {
                uint32_t vb[2][4];
#pragma unroll
                for (int p = 0; p < 2; p++) {
                    int dp = dq * 2 + p;
                    ldsm4t(vb[p], bb + VH_O + (uint32_t)((ks * 16 + t_row) * ROWQ + (dp * 16 + t_col) * 2));
                }
#pragma unroll
                for (int p = 0; p < 2; p++) {
                    int dp = dq * 2 + p;
                    mma_f16(o[dp * 2],     pah, &vb[p][0]);
                    mma_f16(o[dp * 2 + 1], pah, &vb[p][2]);
                }
                if (z) {
#pragma unroll
                    for (int p = 0; p < 2; p++) {
                        int dp = dq * 2 + p;
                        mma_f16(o[dp * 2],     pal, &vb[p][0]);
                        mma_f16(o[dp * 2 + 1], pal, &vb[p][2]);
                    }
                }
            }
        }
    }

    // ---- epilogue: single-fp16 cat writes ----
    const float inv0 = 1.f / l0, inv1 = 1.f / l1;
    const int rq = wm + (lane >> 2);
    const int cb = (lane & 3) * 2;
    float v0[8][2], v1[8][2];
#pragma unroll
    for (int j = 0; j < 8; j++) {
        v0[j][0] = o[j][0] * inv0; v0[j][1] = o[j][1] * inv0;
        v1[j][0] = o[j][2] * inv1; v1[j][1] = o[j][3] * inv1;
    }
    if (z) {
        float sum0 = 0.f, sum1 = 0.f;
#pragma unroll
        for (int j = 0; j < 8; j++) {
            sum0 += v0[j][0] + v0[j][1];
            sum1 += v1[j][0] + v1[j][1];
        }
        sum0 += __shfl_xor_sync(0xffffffffu, sum0, 1);
        sum0 += __shfl_xor_sync(0xffffffffu, sum0, 2);
        sum1 += __shfl_xor_sync(0xffffffffu, sum1, 1);
        sum1 += __shfl_xor_sync(0xffffffffu, sum1, 2);
        float mu0 = sum0 * (1.f / 64.f), mu1 = sum1 * (1.f / 64.f);
        float var0 = 0.f, var1 = 0.f;
#pragma unroll
        for (int j = 0; j < 8; j++) {
            float a0 = v0[j][0] - mu0, a1 = v0[j][1] - mu0;
            float b0 = v1[j][0] - mu1, b1 = v1[j][1] - mu1;
            var0 += a0 * a0 + a1 * a1;
            var1 += b0 * b0 + b1 * b1;
        }
        var0 += __shfl_xor_sync(0xffffffffu, var0, 1);
        var0 += __shfl_xor_sync(0xffffffffu, var0, 2);
        var1 += __shfl_xor_sync(0xffffffffu, var1, 1);
        var1 += __shfl_xor_sync(0xffffffffu, var1, 2);
        float is0 = rsqrtf(var0 * (1.f / 64.f) + 1e-5f);
        float is1 = rsqrtf(var1 * (1.f / 64.f) + 1e-5f);
#pragma unroll
        for (int j = 0; j < 8; j++) {
            int col = j * 8 + cb;
            float g0 = gamma[col], g1 = gamma[col + 1];
            float be0 = beta[col], be1 = beta[col + 1];
            v0[j][0] = (v0[j][0] - mu0) * is0 * g0 + be0;
            v0[j][1] = (v0[j][1] - mu0) * is0 * g1 + be1;
            v1[j][0] = (v1[j][0] - mu1) * is1 * g0 + be0;
            v1[j][1] = (v1[j][1] - mu1) * is1 * g1 + be1;
        }
    }
#pragma unroll
    for (int j = 0; j < 8; j++) {
        int col = j * 8 + cb;
        *(uint32_t*)(cath + (size_t)rq * 128 + col)       = pack2h(v0[j][0], v0[j][1]);
        *(uint32_t*)(cath + (size_t)(rq + 8) * 128 + col) = pack2h(v1[j][0], v1[j][1]);
    }
}

// ================= gate via mma (single-term; single-fp16 cat) =================
#define GR 272
#define GA 0
#define GB 34816
#define GATE_SMEM 52224

__global__ void __launch_bounds__(256, 2)
gate_mma(const float* __restrict__ bg) {
    extern __shared__ char smc[];
    const uint32_t smb = (uint32_t)__cvta_generic_to_shared(smc);
    const int tid = threadIdx.x;
    const int wid = tid >> 5;
    const int lane = tid & 31;
    const int m0 = blockIdx.x * 128;

#pragma unroll
    for (int i = 0; i < 8; i++) {
        int e = tid + i * 256;
        int r = e >> 4, c = e & 15;
        cp16(smb + GA + r * GR + c * 16, g_cath + (size_t)(m0 + r) * 128 + c * 8);
    }
#pragma unroll
    for (int i = 0; i < 4; i++) {
        int e = tid + i * 256;
        int r = (e >> 4) & 63, c = e & 15;
        cp16(smb + GB + r * GR + c * 16, g_Wgt + (size_t)r * 128 + c * 8);
    }
    cp_commit();
    cp_wait0();
    __syncthreads();

    const int lrm = lane & 7;
    const int lmat = lane >> 3;
    const int a_row = lrm + (lmat & 1) * 8;
    const int a_koff = (lmat >> 1) * 16;
    const int b_row = lrm + (lmat >> 1) * 8;
    const int b_koff = (lmat & 1) * 16;
    const int wm = wid * 16;

    float acc[8][4] = {};
#pragma unroll
    for (int ks = 0; ks < 8; ks++) {
        uint32_t ah[4];
        ldsm4(ah, smb + GA + (uint32_t)((wm + a_row) * GR + ks * 32 + a_koff));
        uint32_t b[4][4];
#pragma unroll
        for (int np = 0; np < 4; np++)
            ldsm4(b[np], smb + GB + (uint32_t)((np * 16 + b_row) * GR + ks * 32 + b_koff));
#pragma unroll
        for (int np = 0; np < 4; np++)
#pragma unroll
            for (int hf = 0; hf < 2; hf++)
                mma_f16(acc[np * 2 + hf], ah, &b[np][hf * 2]);
    }

    const int rq = wm + (lane >> 2);
    const int cb = (lane & 3) * 2;
#pragma unroll
    for (int rr = 0; rr < 2; rr++) {
        const int r = rq + rr * 8;
        const int R = m0 + r;
        const int bh = R >> 11;
        const int ss = R & 2047;
        const size_t obase = ((size_t)((bh >> 4) * S_ + ss)) * D_ + (bh & 15) * 64;
#pragma unroll
        for (int j = 0; j < 8; j++) {
            const int col = j * 8 + cb;
            float z0 = acc[j][rr * 2 + 0] + bg[col];
            float z1 = acc[j][rr * 2 + 1] + bg[col + 1];
            float g0 = 1.f / (1.f + __expf(-z0));
            float g1 = 1.f / (1.f + __expf(-z1));
            uint32_t lh = *(uint32_t*)(smc + GA + r * GR + col * 2);
            uint32_t gh = *(uint32_t*)(smc + GA + r * GR + (64 + col) * 2);
            float2 lh2 = __half22float2(*(__half2*)&lh);
            float2 gh2 = __half22float2(*(__half2*)&gh);
            float f0 = g0 * lh2.x + (1.f - g0) * gh2.x;
            float f1 = g1 * lh2.y + (1.f - g1) * gh2.y;
            *(uint32_t*)(g_Fh + obase + col) = pack2h(f0, f1);
        }
    }
}

// ---------------- launch ----------------
extern "C" void kernel_launch(void* const* d_in, const int* in_sizes, int n_in,
                              void* d_out, int out_size) {
    (void)in_sizes; (void)n_in; (void)out_size;
    const float* x   = (const float*)d_in[0];
    const float* Wq  = (const float*)d_in[1];
    const float* Wk  = (const float*)d_in[2];
    const float* Wv  = (const float*)d_in[3];
    const float* Wo  = (const float*)d_in[4];
    const float* bo  = (const float*)d_in[5];
    const float* gam = (const float*)d_in[6];
    const float* bet = (const float*)d_in[7];
    const float* Wg  = (const float*)d_in[8];
    const float* bg  = (const float*)d_in[9];
    float* out = (float*)d_out;

    cudaFuncSetAttribute(gemm_f16,  cudaFuncAttributeMaxDynamicSharedMemorySize, GEMM2_SMEM);
    cudaFuncSetAttribute(flash_mma, cudaFuncAttributeMaxDynamicSharedMemorySize, FLM_SMEM);
    cudaFuncSetAttribute(gate_mma,  cudaFuncAttributeMaxDynamicSharedMemorySize, GATE_SMEM);

    __half *xh, *xl, *fh;
    cudaGetSymbolAddress((void**)&xh, g_Xh);
    cudaGetSymbolAddress((void**)&xl, g_Xl);
    cudaGetSymbolAddress((void**)&fh, g_Fh);

    conv_x<<<(B_ * S_ * D_) / 1024, 256>>>(x);
    conv_wt<<<dim3(32, 32, 4), dim3(32, 8)>>>(Wq, Wk, Wv, Wo);
    conv_wg<<<32, 256>>>(Wg);
    gemm_f16<<<dim3(16, 32, 3), 256, GEMM2_SMEM>>>(xh, xl, nullptr, nullptr, 0);
    topk_gather<<<B_ * H_, 512>>>();
    flash_mma<<<dim3(S_ / 128, B_ * H_, 2), 256, FLM_SMEM>>>(gam, bet);
    gate_mma<<<(B_ * H_ * S_) / 128, 256, GATE_SMEM>>>(bg);
    gemm_f16<<<dim3(16, 32, 1), 256, GEMM2_SMEM>>>(fh, fh, bo, out, 1);
}